// round 7
// baseline (speedup 1.0000x reference)
#include <cuda_runtime.h>
#include <cuda_bf16.h>
#include <math.h>
#include <stdint.h>

#define B_    8
#define S_    2048
#define H_    512
#define G4_   2048
#define NBLK  128

// ---------------------------------------------------------------------------
// Static device scratch (no allocation allowed)
// ---------------------------------------------------------------------------
__device__ float    g_xp[(size_t)B_ * S_ * G4_];      // 128 MiB
__device__ float    g_lstm[(size_t)B_ * S_ * H_];     // 32 MiB
__device__ float    g_scores[(size_t)B_ * S_ * H_];   // 32 MiB
__device__ float    g_logits[(size_t)B_ * S_ * S_];   // 128 MiB
__device__ float    g_hbuf[2][B_ * H_];               // h ping-pong
__device__ unsigned g_bar[S_];                        // per-step barrier counters

__device__ __forceinline__ float sigm(float x) { return 1.0f / (1.0f + expf(-x)); }

// ---------------------------------------------------------------------------
// Zero barrier counters + initial hidden state (runs each launch)
// ---------------------------------------------------------------------------
__global__ void zero_kernel() {
    int i = blockIdx.x * 256 + threadIdx.x;   // grid 32 -> 8192 threads
    if (i < S_) g_bar[i] = 0u;
    float* hb = &g_hbuf[0][0];
    if (i < 2 * B_ * H_) hb[i] = 0.0f;
}

// ---------------------------------------------------------------------------
// SGEMM: C[M,N] = A[M,K] * op(B)  (+ bias[n] + bias2[n])
//   BT=true : B is [N,K] row-major (X @ W^T style)
//   BT=false: B is [K,N] row-major
// Tile 128x128x8, 256 threads, 8x8 per thread, register-prefetch double buffer.
// Requires M%128==0, N%128==0, K%8==0 (true for all uses here).
// ---------------------------------------------------------------------------
template <bool BT>
__global__ void __launch_bounds__(256)
gemm_kernel(const float* __restrict__ A, const float* __restrict__ B,
            float* __restrict__ C,
            const float* __restrict__ bias, const float* __restrict__ bias2,
            int K, int lda, int ldb, int ldc,
            size_t sA, size_t sB, size_t sC)
{
    __shared__ float As[2][8][128];
    __shared__ float Bs[2][8][128];

    const int z = blockIdx.z;
    A += (size_t)z * sA;
    B += (size_t)z * sB;
    C += (size_t)z * sC;

    const int m0 = blockIdx.y * 128;
    const int n0 = blockIdx.x * 128;
    const int tid = threadIdx.x;

    const int arow = tid >> 1;
    const int acol = (tid & 1) << 2;
    const float* Ap = A + (size_t)(m0 + arow) * lda + acol;

    int brow, bcol;
    const float* Bp;
    if (BT) {
        brow = tid >> 1; bcol = (tid & 1) << 2;
        Bp = B + (size_t)(n0 + brow) * ldb + bcol;
    } else {
        brow = tid >> 5; bcol = (tid & 31) << 2;
        Bp = B + (size_t)brow * ldb + n0 + bcol;
    }

    float acc[8][8];
#pragma unroll
    for (int i = 0; i < 8; i++)
#pragma unroll
        for (int j = 0; j < 8; j++) acc[i][j] = 0.0f;

    const int KT = K >> 3;

    // stage 0
    {
        float4 av = *(const float4*)Ap;
        As[0][acol + 0][arow] = av.x; As[0][acol + 1][arow] = av.y;
        As[0][acol + 2][arow] = av.z; As[0][acol + 3][arow] = av.w;
        if (BT) {
            float4 bv = *(const float4*)Bp;
            Bs[0][bcol + 0][brow] = bv.x; Bs[0][bcol + 1][brow] = bv.y;
            Bs[0][bcol + 2][brow] = bv.z; Bs[0][bcol + 3][brow] = bv.w;
        } else {
            *(float4*)&Bs[0][brow][bcol] = *(const float4*)Bp;
        }
    }
    __syncthreads();

    const int tx = tid & 15;
    const int ty = tid >> 4;

    for (int kt = 0; kt < KT; kt++) {
        const int cur = kt & 1;
        const int nxt = cur ^ 1;
        const bool more = (kt + 1) < KT;
        float4 an, bn;
        if (more) {
            an = *(const float4*)(Ap + (kt + 1) * 8);
            if (BT) bn = *(const float4*)(Bp + (kt + 1) * 8);
            else    bn = *(const float4*)(Bp + (size_t)(kt + 1) * 8 * ldb);
        }

#pragma unroll
        for (int k = 0; k < 8; k++) {
            float4 a0 = *(const float4*)&As[cur][k][ty * 8];
            float4 a1 = *(const float4*)&As[cur][k][ty * 8 + 4];
            float4 b0 = *(const float4*)&Bs[cur][k][tx * 8];
            float4 b1 = *(const float4*)&Bs[cur][k][tx * 8 + 4];
            float av_[8] = {a0.x, a0.y, a0.z, a0.w, a1.x, a1.y, a1.z, a1.w};
            float bv_[8] = {b0.x, b0.y, b0.z, b0.w, b1.x, b1.y, b1.z, b1.w};
#pragma unroll
            for (int i = 0; i < 8; i++)
#pragma unroll
                for (int j = 0; j < 8; j++)
                    acc[i][j] = fmaf(av_[i], bv_[j], acc[i][j]);
        }

        if (more) {
            As[nxt][acol + 0][arow] = an.x; As[nxt][acol + 1][arow] = an.y;
            As[nxt][acol + 2][arow] = an.z; As[nxt][acol + 3][arow] = an.w;
            if (BT) {
                Bs[nxt][bcol + 0][brow] = bn.x; Bs[nxt][bcol + 1][brow] = bn.y;
                Bs[nxt][bcol + 2][brow] = bn.z; Bs[nxt][bcol + 3][brow] = bn.w;
            } else {
                *(float4*)&Bs[nxt][brow][bcol] = bn;
            }
            __syncthreads();
        }
    }

    float bv_[8];
#pragma unroll
    for (int j = 0; j < 8; j++) {
        float v = 0.0f;
        if (bias)  v += bias[n0 + tx * 8 + j];
        if (bias2) v += bias2[n0 + tx * 8 + j];
        bv_[j] = v;
    }
#pragma unroll
    for (int i = 0; i < 8; i++) {
        float* Cp = C + (size_t)(m0 + ty * 8 + i) * ldc + n0 + tx * 8;
        float4 o0 = make_float4(acc[i][0] + bv_[0], acc[i][1] + bv_[1],
                                acc[i][2] + bv_[2], acc[i][3] + bv_[3]);
        float4 o1 = make_float4(acc[i][4] + bv_[4], acc[i][5] + bv_[5],
                                acc[i][6] + bv_[6], acc[i][7] + bv_[7]);
        *(float4*)Cp = o0;
        *(float4*)(Cp + 4) = o1;
    }
}

// ---------------------------------------------------------------------------
// Persistent LSTM recurrence.
// 128 blocks x 256 threads, all co-resident. Block blk owns hidden units
// j in [blk*4, blk*4+4); caches its 16 W_hh rows (4 gates x 4 j) in SMEM.
// Per step: stage h (L2, __ldcg) -> SMEM, 16 rows x 16 K-splits dot products
// with 8-batch register accumulators, shuffle-reduce, local gate activation,
// grid-wide barrier on g_bar[t].
// ---------------------------------------------------------------------------
__global__ void __launch_bounds__(256)
lstm_rec_kernel(const float* __restrict__ W_hh)
{
    extern __shared__ float smem[];
    float*  ws      = smem;                       // [16][520] padded
    float4* hs4     = (float4*)(smem + 16 * 520); // [8][128]
    float*  gates_s = smem + 16 * 520 + 4096;     // [16][8]  (row-major, b inner)
    float*  cs      = gates_s + 128;              // [32] = [b][q]

    const int tid = threadIdx.x;
    const int blk = blockIdx.x;
    const int j0  = blk * 4;

    // cache W_hh rows: local row lr = gidx*4 + jj  -> global row gidx*512 + j0 + jj
    for (int i = tid; i < 16 * 128; i += 256) {
        int lr = i >> 7;
        int c4 = i & 127;
        int gi = lr >> 2, jj = lr & 3;
        float4 v = *(const float4*)&W_hh[((size_t)(gi * 512 + j0 + jj)) * 512 + c4 * 4];
        *(float4*)&ws[lr * 520 + c4 * 4] = v;
    }
    if (tid < 32) cs[tid] = 0.0f;
    __syncthreads();

    const int row = tid >> 4;   // 0..15 (= gidx*4 + jj)
    const int ks  = tid & 15;   // K split

    for (int t = 0; t < S_; t++) {
        const int cur = t & 1;

        // prefetch xp for the activation threads (consumed ~2.5k cyc later)
        float xi = 0.f, xf = 0.f, xg = 0.f, xo = 0.f;
        if (tid < 32) {
            int b = tid >> 2, q = tid & 3;
            size_t base = ((size_t)b * S_ + t) * G4_ + (j0 + q);
            xi = g_xp[base];
            xf = g_xp[base + 512];
            xg = g_xp[base + 1024];
            xo = g_xp[base + 1536];
        }

        // stage h (bypass L1: other SMs wrote it last step)
        {
            const float4* hsrc = (const float4*)&g_hbuf[cur][0];
#pragma unroll
            for (int i = 0; i < 4; i++) {
                int x = tid + i * 256;
                hs4[x] = __ldcg(&hsrc[x]);
            }
        }
        __syncthreads();

        // dot: thread (row, ks) handles float4 chunks {ks + m*16 : m=0..7}
        float acc[8];
#pragma unroll
        for (int b = 0; b < 8; b++) acc[b] = 0.0f;
#pragma unroll
        for (int m = 0; m < 8; m++) {
            int k4 = ks + m * 16;
            float4 w = *(const float4*)&ws[row * 520 + k4 * 4];
#pragma unroll
            for (int b = 0; b < 8; b++) {
                float4 h = hs4[b * 128 + k4];
                acc[b] = fmaf(w.x, h.x, acc[b]);
                acc[b] = fmaf(w.y, h.y, acc[b]);
                acc[b] = fmaf(w.z, h.z, acc[b]);
                acc[b] = fmaf(w.w, h.w, acc[b]);
            }
        }
        // reduce across the 16 ks lanes (stays within each 16-lane half)
#pragma unroll
        for (int off = 8; off; off >>= 1)
#pragma unroll
            for (int b = 0; b < 8; b++)
                acc[b] += __shfl_xor_sync(0xffffffffu, acc[b], off);
        if (ks == 0) {
#pragma unroll
            for (int b = 0; b < 8; b++) gates_s[row * 8 + b] = acc[b];
        }
        __syncthreads();

        // activation: thread (b,q), q = local j index
        if (tid < 32) {
            int b = tid >> 2, q = tid & 3;
            float ig = gates_s[(0 + q)  * 8 + b] + xi;
            float fg = gates_s[(4 + q)  * 8 + b] + xf;
            float gg = gates_s[(8 + q)  * 8 + b] + xg;
            float og = gates_s[(12 + q) * 8 + b] + xo;
            float cc = sigm(fg) * cs[tid] + sigm(ig) * tanhf(gg);
            float hh = sigm(og) * tanhf(cc);
            cs[tid] = cc;
            int j = j0 + q;
            g_hbuf[cur ^ 1][b * H_ + j] = hh;
            g_lstm[((size_t)b * S_ + t) * H_ + j] = hh;
        }

        // grid barrier: release h writes, then spin on per-step counter
        __threadfence();
        __syncthreads();
        if (tid == 0) {
            atomicAdd(&g_bar[t], 1u);
            volatile unsigned* p = &g_bar[t];
            while (*p < (unsigned)NBLK) { __nanosleep(64); }
        }
        __syncthreads();
    }
}

// ---------------------------------------------------------------------------
// Row softmax over g_logits: 16384 rows of 2048, one block per row.
// ---------------------------------------------------------------------------
__global__ void __launch_bounds__(256) softmax_kernel() {
    __shared__ float red[8];
    float* p = g_logits + (size_t)blockIdx.x * 2048;
    const int tid = threadIdx.x;

    float4 v0 = *(const float4*)(p + tid * 4);
    float4 v1 = *(const float4*)(p + 1024 + tid * 4);

    float m = fmaxf(fmaxf(fmaxf(v0.x, v0.y), fmaxf(v0.z, v0.w)),
                    fmaxf(fmaxf(v1.x, v1.y), fmaxf(v1.z, v1.w)));
#pragma unroll
    for (int off = 16; off; off >>= 1)
        m = fmaxf(m, __shfl_xor_sync(0xffffffffu, m, off));
    if ((tid & 31) == 0) red[tid >> 5] = m;
    __syncthreads();
    m = red[0];
#pragma unroll
    for (int w = 1; w < 8; w++) m = fmaxf(m, red[w]);
    __syncthreads();

    v0.x = expf(v0.x - m); v0.y = expf(v0.y - m);
    v0.z = expf(v0.z - m); v0.w = expf(v0.w - m);
    v1.x = expf(v1.x - m); v1.y = expf(v1.y - m);
    v1.z = expf(v1.z - m); v1.w = expf(v1.w - m);

    float s = v0.x + v0.y + v0.z + v0.w + v1.x + v1.y + v1.z + v1.w;
#pragma unroll
    for (int off = 16; off; off >>= 1)
        s += __shfl_xor_sync(0xffffffffu, s, off);
    if ((tid & 31) == 0) red[tid >> 5] = s;
    __syncthreads();
    s = red[0];
#pragma unroll
    for (int w = 1; w < 8; w++) s += red[w];

    float inv = 1.0f / s;
    v0.x *= inv; v0.y *= inv; v0.z *= inv; v0.w *= inv;
    v1.x *= inv; v1.y *= inv; v1.z *= inv; v1.w *= inv;
    *(float4*)(p + tid * 4) = v0;
    *(float4*)(p + 1024 + tid * 4) = v1;
}

// ---------------------------------------------------------------------------
// Launch: x -> xp GEMM -> persistent LSTM -> scores GEMM -> logits GEMM
//         -> softmax -> att@V GEMM -> out
// ---------------------------------------------------------------------------
extern "C" void kernel_launch(void* const* d_in, const int* in_sizes, int n_in,
                              void* d_out, int out_size)
{
    const float* x    = (const float*)d_in[0];  // [B,S,I]
    const float* W_ih = (const float*)d_in[1];  // [4H,I]
    const float* W_hh = (const float*)d_in[2];  // [4H,H]
    const float* b_ih = (const float*)d_in[3];  // [4H]
    const float* b_hh = (const float*)d_in[4];  // [4H]
    const float* Wa   = (const float*)d_in[5];  // [H,H]
    const float* ba   = (const float*)d_in[6];  // [H]
    float* out = (float*)d_out;                 // [B,S,H] fp32

    void *p0, *p1, *p2, *p3;
    cudaGetSymbolAddress(&p0, g_xp);
    cudaGetSymbolAddress(&p1, g_lstm);
    cudaGetSymbolAddress(&p2, g_scores);
    cudaGetSymbolAddress(&p3, g_logits);
    float* xp_p     = (float*)p0;
    float* lstm_p   = (float*)p1;
    float* scores_p = (float*)p2;
    float* logits_p = (float*)p3;

    const int REC_SMEM = (16 * 520 + 4096 + 128 + 32) * 4;  // 50304 B
    cudaFuncSetAttribute(lstm_rec_kernel,
                         cudaFuncAttributeMaxDynamicSharedMemorySize, REC_SMEM);

    // reset barrier counters + h0
    zero_kernel<<<32, 256>>>();

    // 1) xp = x @ W_ih^T + b_ih + b_hh       M=16384, N=2048, K=512
    gemm_kernel<true><<<dim3(16, 128, 1), 256>>>(
        x, W_ih, xp_p, b_ih, b_hh, 512, 512, 512, 2048, 0, 0, 0);

    // 2) persistent LSTM recurrence (2048 steps, single launch)
    lstm_rec_kernel<<<NBLK, 256, REC_SMEM>>>(W_hh);

    // 3) scores = lstm @ Wa^T + ba           M=16384, N=512, K=512
    gemm_kernel<true><<<dim3(4, 128, 1), 256>>>(
        lstm_p, Wa, scores_p, ba, nullptr, 512, 512, 512, 512, 0, 0, 0);

    // 4) logits[b] = scores[b] @ scores[b]^T M=2048, N=2048, K=512, batched
    gemm_kernel<true><<<dim3(16, 16, 8), 256>>>(
        scores_p, scores_p, logits_p, nullptr, nullptr,
        512, 512, 512, 2048,
        (size_t)2048 * 512, (size_t)2048 * 512, (size_t)2048 * 2048);

    // 5) att = softmax(logits) row-wise, in place
    softmax_kernel<<<16384, 256>>>();

    // 6) out[b] = att[b] @ lstm[b]           M=2048, N=512, K=2048, batched
    gemm_kernel<false><<<dim3(4, 16, 8), 256>>>(
        logits_p, lstm_p, out, nullptr, nullptr,
        2048, 2048, 512, 512,
        (size_t)2048 * 2048, (size_t)2048 * 512, (size_t)2048 * 512);
}

// round 8
// speedup vs baseline: 1.1387x; 1.1387x over previous
#include <cuda_runtime.h>
#include <cuda_bf16.h>
#include <math.h>
#include <stdint.h>

#define B_    8
#define S_    2048
#define H_    512
#define G4_   2048
#define NBLK  128

// ---------------------------------------------------------------------------
// Static device scratch (no allocation allowed)
// ---------------------------------------------------------------------------
__device__ float    g_xp[(size_t)B_ * S_ * G4_];      // 128 MiB
__device__ float    g_lstm[(size_t)B_ * S_ * H_];     // 32 MiB
__device__ float    g_scores[(size_t)B_ * S_ * H_];   // 32 MiB
__device__ float    g_logits[(size_t)B_ * S_ * S_];   // 128 MiB
__device__ float    g_hbuf[2][B_ * H_];               // h ping-pong
__device__ unsigned g_bar[S_];                        // per-step barrier counters

__device__ __forceinline__ float sigm(float x) { return 1.0f / (1.0f + expf(-x)); }

// packed fp32x2 FMA (sm_100+): d = a*b + d on both lanes
__device__ __forceinline__ void fma2(unsigned long long &d,
                                     unsigned long long a,
                                     unsigned long long b) {
    asm("fma.rn.f32x2 %0, %1, %2, %0;" : "+l"(d) : "l"(a), "l"(b));
}
__device__ __forceinline__ unsigned long long dup2(float v) {
    unsigned long long r;
    asm("mov.b64 %0, {%1, %1};" : "=l"(r) : "f"(v));
    return r;
}
__device__ __forceinline__ float2 upk2(unsigned long long v) {
    float2 r;
    asm("mov.b64 {%0, %1}, %2;" : "=f"(r.x), "=f"(r.y) : "l"(v));
    return r;
}

// ---------------------------------------------------------------------------
// Zero barrier counters + initial hidden state (runs each launch)
// ---------------------------------------------------------------------------
__global__ void zero_kernel() {
    int i = blockIdx.x * 256 + threadIdx.x;   // grid 32 -> 8192 threads
    if (i < S_) g_bar[i] = 0u;
    float* hb = &g_hbuf[0][0];
    if (i < 2 * B_ * H_) hb[i] = 0.0f;
}

// ---------------------------------------------------------------------------
// SGEMM: C[M,N] = A[M,K] * op(B)  (+ bias[n] + bias2[n])
//   BT=true : B is [N,K] row-major (X @ W^T style)
//   BT=false: B is [K,N] row-major
// Tile 128x128x8, 256 threads, 8x8 per thread (acc paired along j as f32x2),
// register-prefetch double buffer. M%128==0, N%128==0, K%8==0.
// ---------------------------------------------------------------------------
template <bool BT>
__global__ void __launch_bounds__(256)
gemm_kernel(const float* __restrict__ A, const float* __restrict__ B,
            float* __restrict__ C,
            const float* __restrict__ bias, const float* __restrict__ bias2,
            int K, int lda, int ldb, int ldc,
            size_t sA, size_t sB, size_t sC)
{
    __shared__ float As[2][8][128];
    __shared__ float Bs[2][8][128];

    const int z = blockIdx.z;
    A += (size_t)z * sA;
    B += (size_t)z * sB;
    C += (size_t)z * sC;

    const int m0 = blockIdx.y * 128;
    const int n0 = blockIdx.x * 128;
    const int tid = threadIdx.x;

    const int arow = tid >> 1;
    const int acol = (tid & 1) << 2;
    const float* Ap = A + (size_t)(m0 + arow) * lda + acol;

    int brow, bcol;
    const float* Bp;
    if (BT) {
        brow = tid >> 1; bcol = (tid & 1) << 2;
        Bp = B + (size_t)(n0 + brow) * ldb + bcol;
    } else {
        brow = tid >> 5; bcol = (tid & 31) << 2;
        Bp = B + (size_t)brow * ldb + n0 + bcol;
    }

    unsigned long long acc2[8][4];
#pragma unroll
    for (int i = 0; i < 8; i++)
#pragma unroll
        for (int j = 0; j < 4; j++) acc2[i][j] = 0ull;

    const int KT = K >> 3;

    // stage 0
    {
        float4 av = *(const float4*)Ap;
        As[0][acol + 0][arow] = av.x; As[0][acol + 1][arow] = av.y;
        As[0][acol + 2][arow] = av.z; As[0][acol + 3][arow] = av.w;
        if (BT) {
            float4 bv = *(const float4*)Bp;
            Bs[0][bcol + 0][brow] = bv.x; Bs[0][bcol + 1][brow] = bv.y;
            Bs[0][bcol + 2][brow] = bv.z; Bs[0][bcol + 3][brow] = bv.w;
        } else {
            *(float4*)&Bs[0][brow][bcol] = *(const float4*)Bp;
        }
    }
    __syncthreads();

    const int tx = tid & 15;
    const int ty = tid >> 4;

    for (int kt = 0; kt < KT; kt++) {
        const int cur = kt & 1;
        const int nxt = cur ^ 1;
        const bool more = (kt + 1) < KT;
        float4 an, bn;
        if (more) {
            an = *(const float4*)(Ap + (kt + 1) * 8);
            if (BT) bn = *(const float4*)(Bp + (kt + 1) * 8);
            else    bn = *(const float4*)(Bp + (size_t)(kt + 1) * 8 * ldb);
        }

#pragma unroll
        for (int k = 0; k < 8; k++) {
            float4 a0 = *(const float4*)&As[cur][k][ty * 8];
            float4 a1 = *(const float4*)&As[cur][k][ty * 8 + 4];
            float4 b0 = *(const float4*)&Bs[cur][k][tx * 8];
            float4 b1 = *(const float4*)&Bs[cur][k][tx * 8 + 4];
            unsigned long long a2[8];
            a2[0] = dup2(a0.x); a2[1] = dup2(a0.y);
            a2[2] = dup2(a0.z); a2[3] = dup2(a0.w);
            a2[4] = dup2(a1.x); a2[5] = dup2(a1.y);
            a2[6] = dup2(a1.z); a2[7] = dup2(a1.w);
            unsigned long long b2[4];
            b2[0] = ((const unsigned long long*)&b0)[0];
            b2[1] = ((const unsigned long long*)&b0)[1];
            b2[2] = ((const unsigned long long*)&b1)[0];
            b2[3] = ((const unsigned long long*)&b1)[1];
#pragma unroll
            for (int i = 0; i < 8; i++)
#pragma unroll
                for (int j = 0; j < 4; j++)
                    fma2(acc2[i][j], a2[i], b2[j]);
        }

        if (more) {
            As[nxt][acol + 0][arow] = an.x; As[nxt][acol + 1][arow] = an.y;
            As[nxt][acol + 2][arow] = an.z; As[nxt][acol + 3][arow] = an.w;
            if (BT) {
                Bs[nxt][bcol + 0][brow] = bn.x; Bs[nxt][bcol + 1][brow] = bn.y;
                Bs[nxt][bcol + 2][brow] = bn.z; Bs[nxt][bcol + 3][brow] = bn.w;
            } else {
                *(float4*)&Bs[nxt][brow][bcol] = bn;
            }
            __syncthreads();
        }
    }

    float bv_[8];
#pragma unroll
    for (int j = 0; j < 8; j++) {
        float v = 0.0f;
        if (bias)  v += bias[n0 + tx * 8 + j];
        if (bias2) v += bias2[n0 + tx * 8 + j];
        bv_[j] = v;
    }
#pragma unroll
    for (int i = 0; i < 8; i++) {
        float* Cp = C + (size_t)(m0 + ty * 8 + i) * ldc + n0 + tx * 8;
        float2 p0 = upk2(acc2[i][0]);
        float2 p1 = upk2(acc2[i][1]);
        float2 p2 = upk2(acc2[i][2]);
        float2 p3 = upk2(acc2[i][3]);
        float4 o0 = make_float4(p0.x + bv_[0], p0.y + bv_[1],
                                p1.x + bv_[2], p1.y + bv_[3]);
        float4 o1 = make_float4(p2.x + bv_[4], p2.y + bv_[5],
                                p3.x + bv_[6], p3.y + bv_[7]);
        *(float4*)Cp = o0;
        *(float4*)(Cp + 4) = o1;
    }
}

// ---------------------------------------------------------------------------
// Persistent LSTM recurrence, v2.
// 128 blocks x 256 threads. Block blk owns hidden units j in [blk*4, blk*4+4),
// caching its 16 W_hh rows in SMEM once.
// Thread layout: rg = tid>>6 (gate 0..3), ks = tid&63 (K split).
// Each thread: 4x8 (jj x batch) f32x2 accumulator tile over K chunks
// k4 = ks + m*64 (m=0,1): 12 LDS.128 per 128 FMA -> LDS ~768 cyc/step.
// Reduce: recursive-halving butterfly (31 SHFL), partials to SMEM,
// 32 activation threads finish gates; grid barrier on g_bar[t].
// ---------------------------------------------------------------------------
__global__ void __launch_bounds__(256, 1)
lstm_rec_kernel(const float* __restrict__ W_hh)
{
    extern __shared__ float smem[];
    float*  ws   = smem;                        // [16][520]
    float4* hs4  = (float4*)(smem + 16 * 520);  // [8][128]
    float*  red  = smem + 16 * 520 + 4096;      // [8 warps][32]
    float*  cs   = red + 8 * 32;                // [32] cell state (b*4+q)

    const int tid  = threadIdx.x;
    const int blk  = blockIdx.x;
    const int j0   = blk * 4;
    const int rg   = tid >> 6;        // gate index 0..3
    const int ks   = tid & 63;        // K split 0..63
    const int wid  = tid >> 5;        // warp 0..7  (= rg*2 + half)
    const int lane = tid & 31;
    const int oidx = __brev(lane) >> 27;   // butterfly output index

    // cache W_hh rows: local row lr = gate*4 + jj -> global row gate*512 + j0 + jj
    for (int i = tid; i < 16 * 128; i += 256) {
        int lr = i >> 7;
        int c4 = i & 127;
        int gi = lr >> 2, jj = lr & 3;
        float4 v = *(const float4*)&W_hh[((size_t)(gi * 512 + j0 + jj)) * 512 + c4 * 4];
        *(float4*)&ws[lr * 520 + c4 * 4] = v;
    }
    if (tid < 32) cs[tid] = 0.0f;
    __syncthreads();

    for (int t = 0; t < S_; t++) {
        const int cur = t & 1;

        // prefetch xp for the activation threads (long-latency, overlaps dot)
        float xi = 0.f, xf = 0.f, xg = 0.f, xo = 0.f;
        if (tid < 32) {
            int b = tid >> 2, q = tid & 3;
            size_t base = ((size_t)b * S_ + t) * G4_ + (j0 + q);
            xi = g_xp[base];
            xf = g_xp[base + 512];
            xg = g_xp[base + 1024];
            xo = g_xp[base + 1536];
        }

        // stage h (bypass L1: other SMs wrote it last step)
        {
            const float4* hsrc = (const float4*)&g_hbuf[cur][0];
#pragma unroll
            for (int i = 0; i < 4; i++) {
                int x = tid + i * 256;
                hs4[x] = __ldcg(&hsrc[x]);
            }
        }
        __syncthreads();

        // dot: acc2[jj][b], pairs along K (f32x2)
        unsigned long long acc2[4][8];
#pragma unroll
        for (int jj = 0; jj < 4; jj++)
#pragma unroll
            for (int b = 0; b < 8; b++) acc2[jj][b] = 0ull;

#pragma unroll
        for (int m = 0; m < 2; m++) {
            const int k4 = ks + m * 64;
            unsigned long long w01[4], w23[4];
#pragma unroll
            for (int jj = 0; jj < 4; jj++) {
                float4 w = *(const float4*)&ws[(rg * 4 + jj) * 520 + k4 * 4];
                w01[jj] = ((const unsigned long long*)&w)[0];
                w23[jj] = ((const unsigned long long*)&w)[1];
            }
#pragma unroll
            for (int b = 0; b < 8; b++) {
                float4 h = hs4[b * 128 + k4];
                unsigned long long h01 = ((const unsigned long long*)&h)[0];
                unsigned long long h23 = ((const unsigned long long*)&h)[1];
#pragma unroll
                for (int jj = 0; jj < 4; jj++) {
                    fma2(acc2[jj][b], w01[jj], h01);
                    fma2(acc2[jj][b], w23[jj], h23);
                }
            }
        }

        // collapse f32x2 pairs -> 32 scalars, index jj*8+b
        float a[32];
#pragma unroll
        for (int jj = 0; jj < 4; jj++)
#pragma unroll
            for (int b = 0; b < 8; b++) {
                float2 p = upk2(acc2[jj][b]);
                a[jj * 8 + b] = p.x + p.y;
            }

        // recursive-halving butterfly reduce: 31 SHFL, lane ends with the
        // full in-warp sum of original element bitrev5(lane)
#pragma unroll
        for (int d = 1, n = 16; d < 32; d <<= 1, n >>= 1) {
            const bool up = (lane & d) != 0;
#pragma unroll
            for (int i = 0; i < 16; i++) {
                if (i < n) {
                    float send = up ? a[i] : a[i + n];
                    float recv = __shfl_xor_sync(0xffffffffu, send, d);
                    a[i] = (up ? a[i + n] : a[i]) + recv;
                }
            }
        }
        red[wid * 32 + oidx] = a[0];
        __syncthreads();

        // activation: thread (b,q); gate g partials from the rg=g warp pair
        if (tid < 32) {
            int b = tid >> 2, q = tid & 3;
            int o = q * 8 + b;
            float ig = red[0 * 32 + o] + red[1 * 32 + o] + xi;
            float fg = red[2 * 32 + o] + red[3 * 32 + o] + xf;
            float gg = red[4 * 32 + o] + red[5 * 32 + o] + xg;
            float og = red[6 * 32 + o] + red[7 * 32 + o] + xo;
            float cc = sigm(fg) * cs[tid] + sigm(ig) * tanhf(gg);
            float hh = sigm(og) * tanhf(cc);
            cs[tid] = cc;
            int j = j0 + q;
            g_hbuf[cur ^ 1][b * H_ + j] = hh;
            g_lstm[((size_t)b * S_ + t) * H_ + j] = hh;
        }

        // grid barrier: release h writes, then spin on per-step counter
        __threadfence();
        __syncthreads();
        if (tid == 0) {
            atomicAdd(&g_bar[t], 1u);
            volatile unsigned* p = &g_bar[t];
            while (*p < (unsigned)NBLK) { __nanosleep(64); }
        }
        __syncthreads();
    }
}

// ---------------------------------------------------------------------------
// Row softmax over g_logits: 16384 rows of 2048, one block per row.
// ---------------------------------------------------------------------------
__global__ void __launch_bounds__(256) softmax_kernel() {
    __shared__ float red[8];
    float* p = g_logits + (size_t)blockIdx.x * 2048;
    const int tid = threadIdx.x;

    float4 v0 = *(const float4*)(p + tid * 4);
    float4 v1 = *(const float4*)(p + 1024 + tid * 4);

    float m = fmaxf(fmaxf(fmaxf(v0.x, v0.y), fmaxf(v0.z, v0.w)),
                    fmaxf(fmaxf(v1.x, v1.y), fmaxf(v1.z, v1.w)));
#pragma unroll
    for (int off = 16; off; off >>= 1)
        m = fmaxf(m, __shfl_xor_sync(0xffffffffu, m, off));
    if ((tid & 31) == 0) red[tid >> 5] = m;
    __syncthreads();
    m = red[0];
#pragma unroll
    for (int w = 1; w < 8; w++) m = fmaxf(m, red[w]);
    __syncthreads();

    v0.x = expf(v0.x - m); v0.y = expf(v0.y - m);
    v0.z = expf(v0.z - m); v0.w = expf(v0.w - m);
    v1.x = expf(v1.x - m); v1.y = expf(v1.y - m);
    v1.z = expf(v1.z - m); v1.w = expf(v1.w - m);

    float s = v0.x + v0.y + v0.z + v0.w + v1.x + v1.y + v1.z + v1.w;
#pragma unroll
    for (int off = 16; off; off >>= 1)
        s += __shfl_xor_sync(0xffffffffu, s, off);
    if ((tid & 31) == 0) red[tid >> 5] = s;
    __syncthreads();
    s = red[0];
#pragma unroll
    for (int w = 1; w < 8; w++) s += red[w];

    float inv = 1.0f / s;
    v0.x *= inv; v0.y *= inv; v0.z *= inv; v0.w *= inv;
    v1.x *= inv; v1.y *= inv; v1.z *= inv; v1.w *= inv;
    *(float4*)(p + tid * 4) = v0;
    *(float4*)(p + 1024 + tid * 4) = v1;
}

// ---------------------------------------------------------------------------
// Launch
// ---------------------------------------------------------------------------
extern "C" void kernel_launch(void* const* d_in, const int* in_sizes, int n_in,
                              void* d_out, int out_size)
{
    const float* x    = (const float*)d_in[0];  // [B,S,I]
    const float* W_ih = (const float*)d_in[1];  // [4H,I]
    const float* W_hh = (const float*)d_in[2];  // [4H,H]
    const float* b_ih = (const float*)d_in[3];  // [4H]
    const float* b_hh = (const float*)d_in[4];  // [4H]
    const float* Wa   = (const float*)d_in[5];  // [H,H]
    const float* ba   = (const float*)d_in[6];  // [H]
    float* out = (float*)d_out;                 // [B,S,H] fp32

    void *p0, *p1, *p2, *p3;
    cudaGetSymbolAddress(&p0, g_xp);
    cudaGetSymbolAddress(&p1, g_lstm);
    cudaGetSymbolAddress(&p2, g_scores);
    cudaGetSymbolAddress(&p3, g_logits);
    float* xp_p     = (float*)p0;
    float* lstm_p   = (float*)p1;
    float* scores_p = (float*)p2;
    float* logits_p = (float*)p3;

    // ws + hs4 + red + cs
    const int REC_SMEM = (16 * 520 + 4096 + 8 * 32 + 32) * 4;
    cudaFuncSetAttribute(lstm_rec_kernel,
                         cudaFuncAttributeMaxDynamicSharedMemorySize, REC_SMEM);

    zero_kernel<<<32, 256>>>();

    // 1) xp = x @ W_ih^T + b_ih + b_hh       M=16384, N=2048, K=512
    gemm_kernel<true><<<dim3(16, 128, 1), 256>>>(
        x, W_ih, xp_p, b_ih, b_hh, 512, 512, 512, 2048, 0, 0, 0);

    // 2) persistent LSTM recurrence (2048 steps, single launch)
    lstm_rec_kernel<<<NBLK, 256, REC_SMEM>>>(W_hh);

    // 3) scores = lstm @ Wa^T + ba           M=16384, N=512, K=512
    gemm_kernel<true><<<dim3(4, 128, 1), 256>>>(
        lstm_p, Wa, scores_p, ba, nullptr, 512, 512, 512, 512, 0, 0, 0);

    // 4) logits[b] = scores[b] @ scores[b]^T M=2048, N=2048, K=512, batched
    gemm_kernel<true><<<dim3(16, 16, 8), 256>>>(
        scores_p, scores_p, logits_p, nullptr, nullptr,
        512, 512, 512, 2048,
        (size_t)2048 * 512, (size_t)2048 * 512, (size_t)2048 * 2048);

    // 5) att = softmax(logits) row-wise, in place
    softmax_kernel<<<16384, 256>>>();

    // 6) out[b] = att[b] @ lstm[b]           M=2048, N=512, K=2048, batched
    gemm_kernel<false><<<dim3(4, 16, 8), 256>>>(
        logits_p, lstm_p, out, nullptr, nullptr,
        2048, 2048, 512, 512,
        (size_t)2048 * 2048, (size_t)2048 * 512, (size_t)2048 * 512);
}

// round 10
// speedup vs baseline: 1.4589x; 1.2812x over previous
#include <cuda_runtime.h>
#include <cuda_bf16.h>
#include <math.h>
#include <stdint.h>

#define B_    8
#define S_    2048
#define H_    512
#define G4_   2048
#define NBLK  128

// ---------------------------------------------------------------------------
// Static device scratch (no allocation allowed)
// ---------------------------------------------------------------------------
__device__ float    g_xp[(size_t)B_ * S_ * G4_];      // 128 MiB
__device__ float    g_lstm[(size_t)B_ * S_ * H_];     // 32 MiB
__device__ float    g_scores[(size_t)B_ * S_ * H_];   // 32 MiB
__device__ float    g_logits[(size_t)B_ * S_ * S_];   // 128 MiB
__device__ float    g_hbuf[2][B_ * H_];               // h ping-pong
__device__ unsigned g_bar[S_];                        // per-step barrier counters

// bf16-split operand buffers
__device__ __align__(16) __nv_bfloat16 g_bufA[(size_t)16384 * 1536];   // 50 MiB
__device__ __align__(16) __nv_bfloat16 g_bufW[(size_t)2048 * 1536];    // 6 MiB
__device__ __align__(16) __nv_bfloat16 g_bufBIG[(size_t)16384 * 6144]; // 201 MiB
__device__ __align__(16) __nv_bfloat16 g_bufT[(size_t)8 * 512 * 6144]; // 50 MiB

__device__ __forceinline__ float sigm(float x) { return 1.0f / (1.0f + expf(-x)); }

__device__ __forceinline__ uint32_t smem_u32(const void* p) {
    uint32_t a;
    asm("{ .reg .u64 t; cvta.to.shared.u64 t, %1; cvt.u32.u64 %0, t; }"
        : "=r"(a) : "l"(p));
    return a;
}

__device__ __forceinline__ void ldm_x4(uint32_t* r, uint32_t addr) {
    asm volatile("ldmatrix.sync.aligned.m8n8.x4.shared.b16 {%0,%1,%2,%3}, [%4];"
        : "=r"(r[0]), "=r"(r[1]), "=r"(r[2]), "=r"(r[3]) : "r"(addr));
}

__device__ __forceinline__ void mma16816(float* c, const uint32_t* a,
                                         const uint32_t* b) {
    asm volatile(
        "mma.sync.aligned.m16n8k16.row.col.f32.bf16.bf16.f32 "
        "{%0,%1,%2,%3}, {%4,%5,%6,%7}, {%8,%9}, {%0,%1,%2,%3};"
        : "+f"(c[0]), "+f"(c[1]), "+f"(c[2]), "+f"(c[3])
        : "r"(a[0]), "r"(a[1]), "r"(a[2]), "r"(a[3]), "r"(b[0]), "r"(b[1]));
}

// ---------------------------------------------------------------------------
// Zero barrier counters + initial hidden state
// ---------------------------------------------------------------------------
__global__ void zero_kernel() {
    int i = blockIdx.x * 256 + threadIdx.x;
    if (i < S_) g_bar[i] = 0u;
    float* hb = &g_hbuf[0][0];
    if (i < 2 * B_ * H_) hb[i] = 0.0f;
}

// ---------------------------------------------------------------------------
// fp32 -> split-bf16 conversion, contiguous [R,K] -> [R,3K]
// amode=1 (A operand): segments (hi, lo, hi)
// amode=0 (B operand): segments (hi, hi, lo)
// ---------------------------------------------------------------------------
__global__ void __launch_bounds__(256)
cvt_split(const float* __restrict__ in, __nv_bfloat16* __restrict__ out,
          int K, int amode)
{
    size_t e = ((size_t)blockIdx.x * 256 + threadIdx.x) * 2;
    size_t r = e / (size_t)K;
    int k = (int)(e - r * (size_t)K);
    float2 x = *(const float2*)(in + e);
    __nv_bfloat16 h0 = __float2bfloat16(x.x);
    __nv_bfloat16 h1 = __float2bfloat16(x.y);
    __nv_bfloat16 l0 = __float2bfloat16(x.x - __bfloat162float(h0));
    __nv_bfloat16 l1 = __float2bfloat16(x.y - __bfloat162float(h1));
    __nv_bfloat162 Hv; Hv.x = h0; Hv.y = h1;
    __nv_bfloat162 Lv; Lv.x = l0; Lv.y = l1;
    __nv_bfloat16* o = out + r * (size_t)(3 * K) + k;
    *(__nv_bfloat162*)o = Hv;
    *(__nv_bfloat162*)(o + K) = amode ? Lv : Hv;
    *(__nv_bfloat162*)(o + 2 * K) = amode ? Hv : Lv;
}

// lstm [b][t][h] -> transposed split-bf16 B operand g_bufT[b][h][3*2048] (hi,hi,lo)
__global__ void __launch_bounds__(256)
cvt_lstmT()
{
    int idx = blockIdx.x * 256 + threadIdx.x;    // 8*512*1024
    int t2 = idx & 1023;
    int n  = (idx >> 10) & 511;
    int b  = idx >> 19;
    int t  = t2 * 2;
    const float* src = g_lstm + ((size_t)(b * 2048 + t)) * 512 + n;
    float x0 = src[0], x1 = src[512];
    __nv_bfloat16 h0 = __float2bfloat16(x0);
    __nv_bfloat16 h1 = __float2bfloat16(x1);
    __nv_bfloat16 l0 = __float2bfloat16(x0 - __bfloat162float(h0));
    __nv_bfloat16 l1 = __float2bfloat16(x1 - __bfloat162float(h1));
    __nv_bfloat162 Hv; Hv.x = h0; Hv.y = h1;
    __nv_bfloat162 Lv; Lv.x = l0; Lv.y = l1;
    __nv_bfloat16* o = g_bufT + ((size_t)(b * 512 + n)) * 6144 + t;
    *(__nv_bfloat162*)o = Hv;
    *(__nv_bfloat162*)(o + 2048) = Hv;
    *(__nv_bfloat162*)(o + 4096) = Lv;
}

// ---------------------------------------------------------------------------
// Tensor-core bf16 GEMM via mma.sync (HMMA, compiles at compute_100):
//   C[M,N] = A'[M,K3] * B'[N,K3]^T (+bias +bias2)
// CTA 128x128, 128 threads = 4 warps (2x2), warp tile 64x64.
// K chunks of 32 bf16, cp.async double-buffered SMEM, 80B-padded rows
// (conflict-free ldmatrix). Requires M%128==0, N%128==0, K3%32==0.
// ---------------------------------------------------------------------------
__global__ void __launch_bounds__(128, 1)
mma_gemm(const __nv_bfloat16* __restrict__ A, const __nv_bfloat16* __restrict__ B,
         float* __restrict__ C,
         const float* __restrict__ bias, const float* __restrict__ bias2,
         int K3, int ldc, size_t sA, size_t sB, size_t sC)
{
    __shared__ __align__(16) char sm[2][2][128 * 80];   // [stage][A/B][row*80]

    const int z = blockIdx.z;
    A += (size_t)z * sA;
    B += (size_t)z * sB;
    C += (size_t)z * sC;
    const int m0 = blockIdx.y * 128;
    const int n0 = blockIdx.x * 128;

    const int tid = threadIdx.x;
    const int lane = tid & 31;
    const int wid = tid >> 5;
    const int wm = wid & 1;        // warp row (64 rows)
    const int wn = wid >> 1;       // warp col (64 cols)

    const int NC = K3 >> 5;

    float acc[4][8][4];
#pragma unroll
    for (int i = 0; i < 4; i++)
#pragma unroll
        for (int j = 0; j < 8; j++)
#pragma unroll
            for (int q = 0; q < 4; q++) acc[i][j][q] = 0.0f;

    // ---- async stage loader: 1024 16B units (512 A + 512 B), 8 per thread
#define LOAD_STAGE(st, ck) do {                                               \
        _Pragma("unroll")                                                     \
        for (int _i = 0; _i < 8; _i++) {                                      \
            int _u = tid + _i * 128;                                          \
            int _ab = _u >> 9;                                                \
            int _v = _u & 511;                                                \
            int _r = _v >> 2, _cu = _v & 3;                                   \
            const __nv_bfloat16* _g = _ab                                     \
                ? B + (size_t)(n0 + _r) * K3 + (ck) * 32 + _cu * 8            \
                : A + (size_t)(m0 + _r) * K3 + (ck) * 32 + _cu * 8;           \
            uint32_t _s = smem_u32(&sm[st][_ab][_r * 80 + _cu * 16]);         \
            asm volatile("cp.async.cg.shared.global [%0], [%1], 16;"          \
                         :: "r"(_s), "l"(_g));                                \
        }                                                                     \
        asm volatile("cp.async.commit_group;" ::: "memory");                  \
    } while (0)

    LOAD_STAGE(0, 0);

    // ldmatrix address components (within a stage buffer)
    const int a_row_in = (lane & 15);             // + wm*64 + mi*16
    const int a_koff   = (lane >> 4) * 16;        // 0 or 16 bytes
    const int b_row_in = (lane & 7) + ((lane >> 4) << 3);  // + wn*64 + t4*16
    const int b_koff   = ((lane >> 3) & 1) * 16;

    for (int c = 0; c < NC; c++) {
        const int buf = c & 1;
        if (c + 1 < NC) {
            LOAD_STAGE(buf ^ 1, c + 1);
            asm volatile("cp.async.wait_group 1;" ::: "memory");
        } else {
            asm volatile("cp.async.wait_group 0;" ::: "memory");
        }
        __syncthreads();

        const uint32_t sAb = smem_u32(&sm[buf][0][0]);
        const uint32_t sBb = smem_u32(&sm[buf][1][0]);

#pragma unroll
        for (int s = 0; s < 2; s++) {      // two k16 steps per 32-chunk
            uint32_t a[4][4];
#pragma unroll
            for (int mi = 0; mi < 4; mi++) {
                uint32_t addr = sAb +
                    (uint32_t)(wm * 64 + mi * 16 + a_row_in) * 80 +
                    s * 32 + a_koff;
                ldm_x4(a[mi], addr);
            }
            uint32_t b[8][2];
#pragma unroll
            for (int t4 = 0; t4 < 4; t4++) {
                uint32_t r[4];
                uint32_t addr = sBb +
                    (uint32_t)(wn * 64 + t4 * 16 + b_row_in) * 80 +
                    s * 32 + b_koff;
                ldm_x4(r, addr);
                b[2 * t4][0] = r[0]; b[2 * t4][1] = r[1];
                b[2 * t4 + 1][0] = r[2]; b[2 * t4 + 1][1] = r[3];
            }
#pragma unroll
            for (int mi = 0; mi < 4; mi++)
#pragma unroll
                for (int nj = 0; nj < 8; nj++)
                    mma16816(acc[mi][nj], a[mi], b[nj]);
        }
        __syncthreads();
    }

    // ---- epilogue
    const int g = lane >> 2, tig = lane & 3;
#pragma unroll
    for (int mi = 0; mi < 4; mi++) {
        const int r0 = m0 + wm * 64 + mi * 16 + g;
#pragma unroll
        for (int nj = 0; nj < 8; nj++) {
            const int col = n0 + wn * 64 + nj * 8 + tig * 2;
            float b0 = 0.0f, b1 = 0.0f;
            if (bias)  { b0 += bias[col];  b1 += bias[col + 1]; }
            if (bias2) { b0 += bias2[col]; b1 += bias2[col + 1]; }
            float2 v0 = make_float2(acc[mi][nj][0] + b0, acc[mi][nj][1] + b1);
            float2 v1 = make_float2(acc[mi][nj][2] + b0, acc[mi][nj][3] + b1);
            *(float2*)(C + (size_t)r0 * ldc + col) = v0;
            *(float2*)(C + (size_t)(r0 + 8) * ldc + col) = v1;
        }
    }
#undef LOAD_STAGE
}

// ---------------------------------------------------------------------------
// Persistent LSTM recurrence (unchanged from R8 best).
// ---------------------------------------------------------------------------
__global__ void __launch_bounds__(256, 1)
lstm_rec_kernel(const float* __restrict__ W_hh)
{
    extern __shared__ float smemf[];
    float*  ws   = smemf;                        // [16][520]
    float4* hs4  = (float4*)(smemf + 16 * 520);  // [8][128]
    float*  red  = smemf + 16 * 520 + 4096;      // [8 warps][32]
    float*  cs   = red + 8 * 32;                 // [32]

    const int tid  = threadIdx.x;
    const int blk  = blockIdx.x;
    const int j0   = blk * 4;
    const int rg   = tid >> 6;
    const int ks   = tid & 63;
    const int wid  = tid >> 5;
    const int lane = tid & 31;
    const int oidx = __brev(lane) >> 27;

    for (int i = tid; i < 16 * 128; i += 256) {
        int lr = i >> 7;
        int c4 = i & 127;
        int gi = lr >> 2, jj = lr & 3;
        float4 v = *(const float4*)&W_hh[((size_t)(gi * 512 + j0 + jj)) * 512 + c4 * 4];
        *(float4*)&ws[lr * 520 + c4 * 4] = v;
    }
    if (tid < 32) cs[tid] = 0.0f;
    __syncthreads();

    for (int t = 0; t < S_; t++) {
        const int cur = t & 1;

        float xi = 0.f, xf = 0.f, xg = 0.f, xo = 0.f;
        if (tid < 32) {
            int b = tid >> 2, q = tid & 3;
            size_t base = ((size_t)b * S_ + t) * G4_ + (j0 + q);
            xi = g_xp[base];
            xf = g_xp[base + 512];
            xg = g_xp[base + 1024];
            xo = g_xp[base + 1536];
        }

        {
            const float4* hsrc = (const float4*)&g_hbuf[cur][0];
#pragma unroll
            for (int i = 0; i < 4; i++) {
                int x = tid + i * 256;
                hs4[x] = __ldcg(&hsrc[x]);
            }
        }
        __syncthreads();

        float acc[4][8];
#pragma unroll
        for (int jj = 0; jj < 4; jj++)
#pragma unroll
            for (int b = 0; b < 8; b++) acc[jj][b] = 0.0f;

#pragma unroll
        for (int m = 0; m < 2; m++) {
            const int k4 = ks + m * 64;
            float4 w[4];
#pragma unroll
            for (int jj = 0; jj < 4; jj++)
                w[jj] = *(const float4*)&ws[(rg * 4 + jj) * 520 + k4 * 4];
#pragma unroll
            for (int b = 0; b < 8; b++) {
                float4 h = hs4[b * 128 + k4];
#pragma unroll
                for (int jj = 0; jj < 4; jj++) {
                    acc[jj][b] = fmaf(w[jj].x, h.x, acc[jj][b]);
                    acc[jj][b] = fmaf(w[jj].y, h.y, acc[jj][b]);
                    acc[jj][b] = fmaf(w[jj].z, h.z, acc[jj][b]);
                    acc[jj][b] = fmaf(w[jj].w, h.w, acc[jj][b]);
                }
            }
        }

        float a[32];
#pragma unroll
        for (int jj = 0; jj < 4; jj++)
#pragma unroll
            for (int b = 0; b < 8; b++) a[jj * 8 + b] = acc[jj][b];

#pragma unroll
        for (int d = 1, n = 16; d < 32; d <<= 1, n >>= 1) {
            const bool up = (lane & d) != 0;
#pragma unroll
            for (int i = 0; i < 16; i++) {
                if (i < n) {
                    float send = up ? a[i] : a[i + n];
                    float recv = __shfl_xor_sync(0xffffffffu, send, d);
                    a[i] = (up ? a[i + n] : a[i]) + recv;
                }
            }
        }
        red[wid * 32 + oidx] = a[0];
        __syncthreads();

        if (tid < 32) {
            int b = tid >> 2, q = tid & 3;
            int o = q * 8 + b;
            float ig = red[0 * 32 + o] + red[1 * 32 + o] + xi;
            float fg = red[2 * 32 + o] + red[3 * 32 + o] + xf;
            float gg = red[4 * 32 + o] + red[5 * 32 + o] + xg;
            float og = red[6 * 32 + o] + red[7 * 32 + o] + xo;
            float cc = sigm(fg) * cs[tid] + sigm(ig) * tanhf(gg);
            float hh = sigm(og) * tanhf(cc);
            cs[tid] = cc;
            int j = j0 + q;
            g_hbuf[cur ^ 1][b * H_ + j] = hh;
            g_lstm[((size_t)b * S_ + t) * H_ + j] = hh;
        }

        __threadfence();
        __syncthreads();
        if (tid == 0) {
            atomicAdd(&g_bar[t], 1u);
            volatile unsigned* p = &g_bar[t];
            while (*p < (unsigned)NBLK) { __nanosleep(64); }
        }
        __syncthreads();
    }
}

// ---------------------------------------------------------------------------
// Row softmax over g_logits: 16384 rows of 2048.
// ---------------------------------------------------------------------------
__global__ void __launch_bounds__(256) softmax_kernel() {
    __shared__ float red[8];
    float* p = g_logits + (size_t)blockIdx.x * 2048;
    const int tid = threadIdx.x;

    float4 v0 = *(const float4*)(p + tid * 4);
    float4 v1 = *(const float4*)(p + 1024 + tid * 4);

    float m = fmaxf(fmaxf(fmaxf(v0.x, v0.y), fmaxf(v0.z, v0.w)),
                    fmaxf(fmaxf(v1.x, v1.y), fmaxf(v1.z, v1.w)));
#pragma unroll
    for (int off = 16; off; off >>= 1)
        m = fmaxf(m, __shfl_xor_sync(0xffffffffu, m, off));
    if ((tid & 31) == 0) red[tid >> 5] = m;
    __syncthreads();
    m = red[0];
#pragma unroll
    for (int w = 1; w < 8; w++) m = fmaxf(m, red[w]);
    __syncthreads();

    v0.x = expf(v0.x - m); v0.y = expf(v0.y - m);
    v0.z = expf(v0.z - m); v0.w = expf(v0.w - m);
    v1.x = expf(v1.x - m); v1.y = expf(v1.y - m);
    v1.z = expf(v1.z - m); v1.w = expf(v1.w - m);

    float s = v0.x + v0.y + v0.z + v0.w + v1.x + v1.y + v1.z + v1.w;
#pragma unroll
    for (int off = 16; off; off >>= 1)
        s += __shfl_xor_sync(0xffffffffu, s, off);
    if ((tid & 31) == 0) red[tid >> 5] = s;
    __syncthreads();
    s = red[0];
#pragma unroll
    for (int w = 1; w < 8; w++) s += red[w];

    float inv = 1.0f / s;
    v0.x *= inv; v0.y *= inv; v0.z *= inv; v0.w *= inv;
    v1.x *= inv; v1.y *= inv; v1.z *= inv; v1.w *= inv;
    *(float4*)(p + tid * 4) = v0;
    *(float4*)(p + 1024 + tid * 4) = v1;
}

// ---------------------------------------------------------------------------
// Launch
// ---------------------------------------------------------------------------
extern "C" void kernel_launch(void* const* d_in, const int* in_sizes, int n_in,
                              void* d_out, int out_size)
{
    const float* x    = (const float*)d_in[0];  // [B,S,I]
    const float* W_ih = (const float*)d_in[1];  // [4H,I]
    const float* W_hh = (const float*)d_in[2];  // [4H,H]
    const float* b_ih = (const float*)d_in[3];  // [4H]
    const float* b_hh = (const float*)d_in[4];  // [4H]
    const float* Wa   = (const float*)d_in[5];  // [H,H]
    const float* ba   = (const float*)d_in[6];  // [H]
    float* out = (float*)d_out;                 // [B,S,H] fp32

    void *p0, *p1, *p2, *p3, *pa, *pw, *pbig, *pt;
    cudaGetSymbolAddress(&p0, g_xp);
    cudaGetSymbolAddress(&p1, g_lstm);
    cudaGetSymbolAddress(&p2, g_scores);
    cudaGetSymbolAddress(&p3, g_logits);
    cudaGetSymbolAddress(&pa, g_bufA);
    cudaGetSymbolAddress(&pw, g_bufW);
    cudaGetSymbolAddress(&pbig, g_bufBIG);
    cudaGetSymbolAddress(&pt, g_bufT);
    float* xp_p     = (float*)p0;
    float* lstm_p   = (float*)p1;
    float* scores_p = (float*)p2;
    float* logits_p = (float*)p3;
    __nv_bfloat16* bufA   = (__nv_bfloat16*)pa;
    __nv_bfloat16* bufW   = (__nv_bfloat16*)pw;
    __nv_bfloat16* bufBIG = (__nv_bfloat16*)pbig;
    __nv_bfloat16* bufT   = (__nv_bfloat16*)pt;

    const int REC_SMEM = (16 * 520 + 4096 + 8 * 32 + 32) * 4;
    cudaFuncSetAttribute(lstm_rec_kernel,
                         cudaFuncAttributeMaxDynamicSharedMemorySize, REC_SMEM);

    zero_kernel<<<32, 256>>>();

    // 1) xp = x @ W_ih^T + b_ih + b_hh       M=16384, N=2048, K3=1536
    cvt_split<<<16384, 256>>>(x, bufA, 512, 1);
    cvt_split<<<2048, 256>>>(W_ih, bufW, 512, 0);
    mma_gemm<<<dim3(16, 128, 1), 128>>>(
        bufA, bufW, xp_p, b_ih, b_hh, 1536, 2048, 0, 0, 0);

    // 2) persistent LSTM recurrence
    lstm_rec_kernel<<<NBLK, 256, REC_SMEM>>>(W_hh);

    // 3) scores = lstm @ Wa^T + ba           M=16384, N=512, K3=1536
    cvt_split<<<16384, 256>>>(lstm_p, bufA, 512, 1);
    cvt_split<<<512, 256>>>(Wa, bufW, 512, 0);
    mma_gemm<<<dim3(4, 128, 1), 128>>>(
        bufA, bufW, scores_p, ba, nullptr, 1536, 512, 0, 0, 0);

    // 4) logits[b] = scores[b] @ scores[b]^T M=2048, N=2048, K3=1536, batched
    cvt_split<<<16384, 256>>>(scores_p, bufA, 512, 1);
    cvt_split<<<16384, 256>>>(scores_p, bufBIG, 512, 0);
    mma_gemm<<<dim3(16, 16, 8), 128>>>(
        bufA, bufBIG, logits_p, nullptr, nullptr, 1536, 2048,
        (size_t)2048 * 1536, (size_t)2048 * 1536, (size_t)2048 * 2048);

    // 5) att = softmax(logits) in place
    softmax_kernel<<<16384, 256>>>();

    // 6) out[b] = att[b] @ lstm[b]           M=2048, N=512, K3=6144, batched
    cvt_split<<<65536, 256>>>(logits_p, bufBIG, 2048, 1);
    cvt_lstmT<<<16384, 256>>>();
    mma_gemm<<<dim3(4, 16, 8), 128>>>(
        bufBIG, bufT, out, nullptr, nullptr, 6144, 512,
        (size_t)2048 * 6144, (size_t)512 * 6144, (size_t)2048 * 512);
}